// round 4
// baseline (speedup 1.0000x reference)
#include <cuda_runtime.h>
#include <cstdint>

#define Tn 4000
#define Bn 16
#define Cn 256
#define G4 1024        // 4*C
#define Mn (Tn*Bn)     // 64000
#define NLAYER 12

// ---------------- scratch (device globals: allocation-free) ----------------
__device__ float g_Xa[(size_t)Mn * Cn];
__device__ float g_Xb[(size_t)Mn * Cn];
__device__ float g_GX[(size_t)Mn * G4];
__device__ float g_bias[NLAYER * G4];

// ---------------- packed f32x2 helpers ----------------
__device__ __forceinline__ void ffma2(unsigned long long& d, unsigned long long a, unsigned long long b) {
    asm("fma.rn.f32x2 %0, %1, %2, %0;" : "+l"(d) : "l"(a), "l"(b));
}
__device__ __forceinline__ unsigned long long pk(float a, float b) {
    unsigned long long r; asm("mov.b64 %0, {%1,%2};" : "=l"(r) : "f"(a), "f"(b)); return r;
}
__device__ __forceinline__ float2 unpk(unsigned long long v) {
    float2 r; asm("mov.b64 {%0,%1}, %2;" : "=f"(r.x), "=f"(r.y) : "l"(v)); return r;
}

__device__ __forceinline__ float sig_f(float x) {
    return __fdividef(1.f, 1.f + __expf(-x));
}
__device__ __forceinline__ float tanh_f(float x) {
    float z = __expf(-2.f * fabsf(x));
    float t = __fdividef(1.f - z, 1.f + z);
    return (x < 0.f) ? -t : t;
}

// ---------------- cluster / mbarrier primitives ----------------
__device__ __forceinline__ void st_peer_v4(unsigned laddr, unsigned peer, float4 v) {
    asm volatile(
        "{\n\t.reg .u32 ra;\n\t"
        "mapa.shared::cluster.u32 ra, %0, %1;\n\t"
        "st.shared::cluster.v4.f32 [ra], {%2,%3,%4,%5};\n\t}"
        :: "r"(laddr), "r"(peer), "f"(v.x), "f"(v.y), "f"(v.z), "f"(v.w) : "memory");
}
__device__ __forceinline__ void mbar_init(unsigned a, unsigned cnt) {
    asm volatile("mbarrier.init.shared.b64 [%0], %1;" :: "r"(a), "r"(cnt) : "memory");
}
__device__ __forceinline__ void mbar_arrive_local_rel(unsigned a) {
    asm volatile("mbarrier.arrive.release.cluster.shared::cta.b64 _, [%0];"
                 :: "r"(a) : "memory");
}
__device__ __forceinline__ void mbar_arrive_peer_rel(unsigned a_local, unsigned peer) {
    asm volatile(
        "{\n\t.reg .u32 ra;\n\t"
        "mapa.shared::cluster.u32 ra, %0, %1;\n\t"
        "mbarrier.arrive.release.cluster.shared::cluster.b64 _, [ra];\n\t}"
        :: "r"(a_local), "r"(peer) : "memory");
}
__device__ __forceinline__ void mbar_wait(unsigned a, unsigned parity) {
    asm volatile(
        "{\n\t.reg .pred P;\n"
        "W%=:\n\t"
        "mbarrier.try_wait.parity.acquire.cluster.shared::cta.b64 P, [%0], %1, 0x989680;\n\t"
        "@P bra D%=;\n\t"
        "bra W%=;\n"
        "D%=:\n\t}"
        :: "r"(a), "r"(parity) : "memory");
}
#define CLUSTER_SYNC() do { \
    asm volatile("barrier.cluster.arrive.aligned;" ::: "memory"); \
    asm volatile("barrier.cluster.wait.aligned;" ::: "memory"); } while (0)

// ---------------- tiny bias precompute (also shifts ncu launch window) ----------------
__global__ void bias_kernel(const float* __restrict__ bih, const float* __restrict__ bhh,
                            float* __restrict__ out) {
    int i = blockIdx.x * 256 + threadIdx.x;
    out[i] = bih[i] + bhh[i];
}

// ---------------- transpose in: x(B,C,L) -> X[t][b][c] ----------------
__global__ void tin_kernel(const float* __restrict__ x, float* __restrict__ X) {
    __shared__ float tile[32][33];
    int t0 = blockIdx.x * 32, c0 = blockIdx.y * 32, b = blockIdx.z;
    int tx = threadIdx.x, ty = threadIdx.y;
    #pragma unroll
    for (int i = 0; i < 32; i += 8)
        tile[ty + i][tx] = x[(size_t)b * Cn * Tn + (size_t)(c0 + ty + i) * Tn + t0 + tx];
    __syncthreads();
    #pragma unroll
    for (int i = 0; i < 32; i += 8)
        X[(size_t)(t0 + ty + i) * Bn * Cn + b * Cn + c0 + tx] = tile[tx][ty + i];
}

// ---------------- transpose out: X[t][b][c] -> out(B,C,L) ----------------
__global__ void tout_kernel(const float* __restrict__ X, float* __restrict__ out) {
    __shared__ float tile[32][33];
    int t0 = blockIdx.x * 32, c0 = blockIdx.y * 32, b = blockIdx.z;
    int tx = threadIdx.x, ty = threadIdx.y;
    #pragma unroll
    for (int i = 0; i < 32; i += 8)
        tile[ty + i][tx] = X[(size_t)(t0 + ty + i) * Bn * Cn + b * Cn + c0 + tx];
    __syncthreads();
    #pragma unroll
    for (int i = 0; i < 32; i += 8)
        out[(size_t)b * Cn * Tn + (size_t)(c0 + ty + i) * Tn + t0 + tx] = tile[tx][ty + i];
}

// ---------------- gx GEMM: GX[m][n] = X[m][k]*W[n][k] + bias[n] ----------------
__global__ __launch_bounds__(256, 2) void gemm_gx(
    const float* __restrict__ X, const float* __restrict__ W,
    const float* __restrict__ bsum, float* __restrict__ GXo)
{
    __shared__ __align__(16) float As[2][8][128];
    __shared__ __align__(16) float Bs[2][8][128];
    const int m0 = blockIdx.y * 128;
    const int n0 = blockIdx.x * 128;
    const int tid = threadIdx.x;
    const int tx = tid & 15, ty = tid >> 4;
    const int lr = tid >> 1;           // 0..127
    const int lk = (tid & 1) * 4;      // 0 or 4

    const float* Ag = X + (size_t)(m0 + lr) * 256 + lk;
    const float* Bg = W + (size_t)(n0 + lr) * 256 + lk;

    auto load_stage = [&](int s, int kc) {
        float4 av = *reinterpret_cast<const float4*>(Ag + kc * 8);
        float4 bv = *reinterpret_cast<const float4*>(Bg + kc * 8);
        As[s][lk + 0][lr] = av.x; As[s][lk + 1][lr] = av.y;
        As[s][lk + 2][lr] = av.z; As[s][lk + 3][lr] = av.w;
        Bs[s][lk + 0][lr] = bv.x; Bs[s][lk + 1][lr] = bv.y;
        Bs[s][lk + 2][lr] = bv.z; Bs[s][lk + 3][lr] = bv.w;
    };

    unsigned long long acc[8][4];
    #pragma unroll
    for (int i = 0; i < 8; i++)
        #pragma unroll
        for (int j = 0; j < 4; j++) acc[i][j] = 0ull;

    load_stage(0, 0);
    __syncthreads();

    for (int kc = 0; kc < 32; ++kc) {
        int s = kc & 1;
        if (kc < 31) load_stage(s ^ 1, kc + 1);
        #pragma unroll
        for (int k = 0; k < 8; k++) {
            float4 a0 = *reinterpret_cast<const float4*>(&As[s][k][ty * 8]);
            float4 a1 = *reinterpret_cast<const float4*>(&As[s][k][ty * 8 + 4]);
            float4 b0 = *reinterpret_cast<const float4*>(&Bs[s][k][tx * 8]);
            float4 b1 = *reinterpret_cast<const float4*>(&Bs[s][k][tx * 8 + 4]);
            unsigned long long bb0 = pk(b0.x, b0.y), bb1 = pk(b0.z, b0.w);
            unsigned long long bb2 = pk(b1.x, b1.y), bb3 = pk(b1.z, b1.w);
            float av[8] = {a0.x, a0.y, a0.z, a0.w, a1.x, a1.y, a1.z, a1.w};
            #pragma unroll
            for (int i = 0; i < 8; i++) {
                unsigned long long aa = pk(av[i], av[i]);
                ffma2(acc[i][0], aa, bb0);
                ffma2(acc[i][1], aa, bb1);
                ffma2(acc[i][2], aa, bb2);
                ffma2(acc[i][3], aa, bb3);
            }
        }
        __syncthreads();
    }

    float bias[8];
    #pragma unroll
    for (int j = 0; j < 8; j++) bias[j] = __ldg(&bsum[n0 + tx * 8 + j]);
    #pragma unroll
    for (int i = 0; i < 8; i++) {
        size_t m = (size_t)(m0 + ty * 8 + i);
        float o[8];
        #pragma unroll
        for (int jp = 0; jp < 4; jp++) {
            float2 v = unpk(acc[i][jp]);
            o[2 * jp] = v.x + bias[2 * jp];
            o[2 * jp + 1] = v.y + bias[2 * jp + 1];
        }
        float4* dst = reinterpret_cast<float4*>(&GXo[m * 1024 + n0 + tx * 8]);
        dst[0] = make_float4(o[0], o[1], o[2], o[3]);
        dst[1] = make_float4(o[4], o[5], o[6], o[7]);
    }
}

// ---------------- persistent LSTM scan (mbarrier exchange) ----------------
// 16 clusters of 8 CTAs (cluster = one batch element). CTA rank owns hidden
// units [rank*32, rank*32+32) for all 4 gates = 128 W_hh rows in registers.
// 256 threads / 8 warps: warp w, lane: lo=lane&15, kh=lane>>4.
//   row r = w*16+lo (0..127), K split in two halves by kh, reduced by shfl.xor 16.
// Exchange: warp0 computes h, lanes<8 push 128B to each peer via st.shared::cluster.v4,
// signaled with release-arrives on each peer's mbarrier (count = 32 local + 7 remote).
__global__ void __cluster_dims__(8, 1, 1) __launch_bounds__(256, 1)
scan_kernel(const float* __restrict__ Xin, const float* __restrict__ GX,
            const float* __restrict__ Whh, float* __restrict__ Xout, int is_even)
{
    unsigned rank;
    asm("mov.u32 %0, %%cluster_ctarank;" : "=r"(rank));
    const int b = blockIdx.x >> 3;
    const int tid = threadIdx.x;
    const int warp = tid >> 5, lane = tid & 31;
    const int lo = lane & 15, kh = lane >> 4;
    const int r = warp * 16 + lo;           // 0..127
    const int gidx = r >> 5, u = r & 31;
    const int grow = gidx * 256 + (int)rank * 32 + u;

    __shared__ __align__(16) float h_s[2][256];
    __shared__ float act_s[128];
    __shared__ __align__(8) unsigned long long bar[1];

    const unsigned sb    = (unsigned)__cvta_generic_to_shared(&h_s[0][0]);
    const unsigned bar_a = (unsigned)__cvta_generic_to_shared(&bar[0]);

    // 128 fp32 weights per thread, register-resident
    ulonglong2 w[32];
    const ulonglong2* wp = reinterpret_cast<const ulonglong2*>(Whh + (size_t)grow * 256 + kh * 128);
    #pragma unroll
    for (int i = 0; i < 32; i++) w[i] = wp[i];

    h_s[0][tid] = 0.f;
    if (tid == 0) mbar_init(bar_a, 39);
    float c_state = 0.f;
    __syncthreads();
    CLUSTER_SYNC();   // publish mbarrier init + zeroed h to cluster

    const float* gxp = GX + (size_t)b * 1024 + grow;
    float gxv = (kh == 0) ? __ldg(gxp) : 0.f;

    for (int t = 0; t < Tn; ++t) {
        if (t) mbar_wait(bar_a, (t - 1) & 1);

        // prefetch next step's gx (consumed ~1 step later -> DRAM hidden)
        float gx_n = 0.f;
        if (kh == 0 && t + 1 < Tn) gx_n = __ldg(gxp + (size_t)(t + 1) * (Bn * G4));
        int src, dst;
        if (is_even) { dst = (t % 400) * 10 + (t / 400); src = dst; }
        else         { src = t; dst = Tn - 1 - t; }
        float xres = 0.f;
        if (tid < 32)
            xres = __ldg(Xin + ((size_t)src * Bn + b) * Cn + (int)rank * 32 + tid);

        // split-K dot (128 MACs/thread via FFMA2), halves reduced by shfl
        const int par = t & 1;
        const ulonglong2* h2 = reinterpret_cast<const ulonglong2*>(&h_s[par][kh << 7]);
        unsigned long long a0 = 0ull, a1 = 0ull, a2 = 0ull, a3 = 0ull;
        #pragma unroll
        for (int i = 0; i < 32; i += 4) {
            ulonglong2 x0 = h2[i], x1 = h2[i + 1], x2 = h2[i + 2], x3 = h2[i + 3];
            ffma2(a0, w[i].x,     x0.x); ffma2(a1, w[i].y,     x0.y);
            ffma2(a2, w[i + 1].x, x1.x); ffma2(a3, w[i + 1].y, x1.y);
            ffma2(a0, w[i + 2].x, x2.x); ffma2(a1, w[i + 2].y, x2.y);
            ffma2(a2, w[i + 3].x, x3.x); ffma2(a3, w[i + 3].y, x3.y);
        }
        float2 f0 = unpk(a0), f1 = unpk(a1), f2 = unpk(a2), f3 = unpk(a3);
        float partial = ((f0.x + f0.y) + (f1.x + f1.y)) + ((f2.x + f2.y) + (f3.x + f3.y));
        partial += __shfl_xor_sync(0xffffffffu, partial, 16);

        if (kh == 0) {
            float tot = partial + gxv;
            act_s[r] = (gidx == 2) ? tanh_f(tot) : sig_f(tot);
        }
        gxv = gx_n;
        __syncthreads();

        if (tid < 32) {
            float iv = act_s[tid], fv = act_s[32 + tid], gv = act_s[64 + tid], ov = act_s[96 + tid];
            c_state = fv * c_state + iv * gv;
            float hv = ov * tanh_f(c_state);
            const int nb = par ^ 1;
            const int col = (int)rank * 32 + tid;
            h_s[nb][col] = hv;
            __syncwarp();
            if (t + 1 < Tn) {
                mbar_arrive_local_rel(bar_a);   // orders this thread's h_s store
                if (lane < 8 && lane != (int)rank) {
                    unsigned hb = sb + (unsigned)((nb * 256 + (int)rank * 32) * 4);
                    #pragma unroll
                    for (int k = 0; k < 8; k++) {
                        float4 v = *reinterpret_cast<const float4*>(&h_s[nb][(int)rank * 32 + 4 * k]);
                        st_peer_v4(hb + 16u * k, (unsigned)lane, v);
                    }
                    mbar_arrive_peer_rel(bar_a, (unsigned)lane);
                }
            }
            Xout[((size_t)dst * Bn + b) * Cn + col] = xres + hv;
        }
    }
}

// ---------------- launch ----------------
extern "C" void kernel_launch(void* const* d_in, const int* in_sizes, int n_in,
                              void* d_out, int out_size) {
    const float* x    = (const float*)d_in[0];
    const float* w_ih = (const float*)d_in[1];
    const float* w_hh = (const float*)d_in[2];
    const float* b_ih = (const float*)d_in[3];
    const float* b_hh = (const float*)d_in[4];

    float *Xa, *Xb, *GXp, *Bp;
    cudaGetSymbolAddress((void**)&Xa, g_Xa);
    cudaGetSymbolAddress((void**)&Xb, g_Xb);
    cudaGetSymbolAddress((void**)&GXp, g_GX);
    cudaGetSymbolAddress((void**)&Bp, g_bias);
    float* Xbuf[2] = {Xa, Xb};

    bias_kernel<<<NLAYER * G4 / 256, 256>>>(b_ih, b_hh, Bp);

    dim3 tgrid(Tn / 32, Cn / 32, Bn), tblk(32, 8);
    tin_kernel<<<tgrid, tblk>>>(x, Xbuf[0]);

    int cur = 0;
    for (int l = 0; l < NLAYER; ++l) {
        gemm_gx<<<dim3(G4 / 128, Mn / 128), 256>>>(
            Xbuf[cur], w_ih + (size_t)l * G4 * Cn, Bp + (size_t)l * G4, GXp);
        scan_kernel<<<128, 256>>>(
            Xbuf[cur], GXp, w_hh + (size_t)l * G4 * Cn,
            Xbuf[cur ^ 1], (l & 1) == 0 ? 1 : 0);
        cur ^= 1;
    }

    tout_kernel<<<tgrid, tblk>>>(Xbuf[cur], (float*)d_out);
}

// round 5
// speedup vs baseline: 1.0656x; 1.0656x over previous
#include <cuda_runtime.h>
#include <cstdint>

#define Tn 4000
#define Bn 16
#define Cn 256
#define G4 1024        // 4*C
#define Mn (Tn*Bn)     // 64000
#define NLAYER 12

// ---------------- scratch (device globals: allocation-free) ----------------
__device__ float g_Xa[(size_t)Mn * Cn];
__device__ float g_Xb[(size_t)Mn * Cn];
__device__ float g_GX[(size_t)Mn * G4];
__device__ float g_bias[NLAYER * G4];

// ---------------- packed f32x2 helpers ----------------
__device__ __forceinline__ void ffma2(unsigned long long& d, unsigned long long a, unsigned long long b) {
    asm("fma.rn.f32x2 %0, %1, %2, %0;" : "+l"(d) : "l"(a), "l"(b));
}
__device__ __forceinline__ unsigned long long pk(float a, float b) {
    unsigned long long r; asm("mov.b64 %0, {%1,%2};" : "=l"(r) : "f"(a), "f"(b)); return r;
}
__device__ __forceinline__ float2 unpk(unsigned long long v) {
    float2 r; asm("mov.b64 {%0,%1}, %2;" : "=f"(r.x), "=f"(r.y) : "l"(v)); return r;
}

__device__ __forceinline__ float sig_f(float x) {
    return __fdividef(1.f, 1.f + __expf(-x));
}
__device__ __forceinline__ float tanh_f(float x) {
    float z = __expf(-2.f * fabsf(x));
    float t = __fdividef(1.f - z, 1.f + z);
    return (x < 0.f) ? -t : t;
}

// ---------------- cluster primitives ----------------
__device__ __forceinline__ void st_peer_v4(unsigned laddr, unsigned peer, float4 v) {
    asm volatile(
        "{\n\t.reg .u32 ra;\n\t"
        "mapa.shared::cluster.u32 ra, %0, %1;\n\t"
        "st.shared::cluster.v4.f32 [ra], {%2,%3,%4,%5};\n\t}"
        :: "r"(laddr), "r"(peer), "f"(v.x), "f"(v.y), "f"(v.z), "f"(v.w) : "memory");
}
// release-store a flag word into a PEER CTA's smem (orders this thread's prior
// cluster stores before the flag at cluster scope)
__device__ __forceinline__ void st_flag_peer_rel(unsigned laddr, unsigned peer, unsigned v) {
    asm volatile(
        "{\n\t.reg .u32 ra;\n\t"
        "mapa.shared::cluster.u32 ra, %0, %1;\n\t"
        "st.release.cluster.shared::cluster.u32 [ra], %2;\n\t}"
        :: "r"(laddr), "r"(peer), "r"(v) : "memory");
}
// release-store a flag word into OWN smem (publishes warp's h stores to other warps)
__device__ __forceinline__ void st_flag_local_rel(unsigned laddr, unsigned v) {
    asm volatile("st.release.cluster.shared::cta.u32 [%0], %1;"
                 :: "r"(laddr), "r"(v) : "memory");
}
__device__ __forceinline__ unsigned ld_flag_acq(unsigned laddr) {
    unsigned v;
    asm volatile("ld.acquire.cluster.shared::cta.u32 %0, [%1];"
                 : "=r"(v) : "r"(laddr) : "memory");
    return v;
}
#define CLUSTER_SYNC() do { \
    asm volatile("barrier.cluster.arrive.aligned;" ::: "memory"); \
    asm volatile("barrier.cluster.wait.aligned;" ::: "memory"); } while (0)

// ---------------- tiny bias precompute ----------------
__global__ void bias_kernel(const float* __restrict__ bih, const float* __restrict__ bhh,
                            float* __restrict__ out) {
    int i = blockIdx.x * 256 + threadIdx.x;
    out[i] = bih[i] + bhh[i];
}

// ---------------- transpose in: x(B,C,L) -> X[t][b][c] ----------------
__global__ void tin_kernel(const float* __restrict__ x, float* __restrict__ X) {
    __shared__ float tile[32][33];
    int t0 = blockIdx.x * 32, c0 = blockIdx.y * 32, b = blockIdx.z;
    int tx = threadIdx.x, ty = threadIdx.y;
    #pragma unroll
    for (int i = 0; i < 32; i += 8)
        tile[ty + i][tx] = x[(size_t)b * Cn * Tn + (size_t)(c0 + ty + i) * Tn + t0 + tx];
    __syncthreads();
    #pragma unroll
    for (int i = 0; i < 32; i += 8)
        X[(size_t)(t0 + ty + i) * Bn * Cn + b * Cn + c0 + tx] = tile[tx][ty + i];
}

// ---------------- transpose out: X[t][b][c] -> out(B,C,L) ----------------
__global__ void tout_kernel(const float* __restrict__ X, float* __restrict__ out) {
    __shared__ float tile[32][33];
    int t0 = blockIdx.x * 32, c0 = blockIdx.y * 32, b = blockIdx.z;
    int tx = threadIdx.x, ty = threadIdx.y;
    #pragma unroll
    for (int i = 0; i < 32; i += 8)
        tile[ty + i][tx] = X[(size_t)(t0 + ty + i) * Bn * Cn + b * Cn + c0 + tx];
    __syncthreads();
    #pragma unroll
    for (int i = 0; i < 32; i += 8)
        out[(size_t)b * Cn * Tn + (size_t)(c0 + ty + i) * Tn + t0 + tx] = tile[tx][ty + i];
}

// ---------------- gx GEMM: GX[m][n] = X[m][k]*W[n][k] + bias[n] ----------------
__global__ __launch_bounds__(256, 2) void gemm_gx(
    const float* __restrict__ X, const float* __restrict__ W,
    const float* __restrict__ bsum, float* __restrict__ GXo)
{
    __shared__ __align__(16) float As[2][8][128];
    __shared__ __align__(16) float Bs[2][8][128];
    const int m0 = blockIdx.y * 128;
    const int n0 = blockIdx.x * 128;
    const int tid = threadIdx.x;
    const int tx = tid & 15, ty = tid >> 4;
    const int lr = tid >> 1;           // 0..127
    const int lk = (tid & 1) * 4;      // 0 or 4

    const float* Ag = X + (size_t)(m0 + lr) * 256 + lk;
    const float* Bg = W + (size_t)(n0 + lr) * 256 + lk;

    auto load_stage = [&](int s, int kc) {
        float4 av = *reinterpret_cast<const float4*>(Ag + kc * 8);
        float4 bv = *reinterpret_cast<const float4*>(Bg + kc * 8);
        As[s][lk + 0][lr] = av.x; As[s][lk + 1][lr] = av.y;
        As[s][lk + 2][lr] = av.z; As[s][lk + 3][lr] = av.w;
        Bs[s][lk + 0][lr] = bv.x; Bs[s][lk + 1][lr] = bv.y;
        Bs[s][lk + 2][lr] = bv.z; Bs[s][lk + 3][lr] = bv.w;
    };

    unsigned long long acc[8][4];
    #pragma unroll
    for (int i = 0; i < 8; i++)
        #pragma unroll
        for (int j = 0; j < 4; j++) acc[i][j] = 0ull;

    load_stage(0, 0);
    __syncthreads();

    for (int kc = 0; kc < 32; ++kc) {
        int s = kc & 1;
        if (kc < 31) load_stage(s ^ 1, kc + 1);
        #pragma unroll
        for (int k = 0; k < 8; k++) {
            float4 a0 = *reinterpret_cast<const float4*>(&As[s][k][ty * 8]);
            float4 a1 = *reinterpret_cast<const float4*>(&As[s][k][ty * 8 + 4]);
            float4 b0 = *reinterpret_cast<const float4*>(&Bs[s][k][tx * 8]);
            float4 b1 = *reinterpret_cast<const float4*>(&Bs[s][k][tx * 8 + 4]);
            unsigned long long bb0 = pk(b0.x, b0.y), bb1 = pk(b0.z, b0.w);
            unsigned long long bb2 = pk(b1.x, b1.y), bb3 = pk(b1.z, b1.w);
            float av[8] = {a0.x, a0.y, a0.z, a0.w, a1.x, a1.y, a1.z, a1.w};
            #pragma unroll
            for (int i = 0; i < 8; i++) {
                unsigned long long aa = pk(av[i], av[i]);
                ffma2(acc[i][0], aa, bb0);
                ffma2(acc[i][1], aa, bb1);
                ffma2(acc[i][2], aa, bb2);
                ffma2(acc[i][3], aa, bb3);
            }
        }
        __syncthreads();
    }

    float bias[8];
    #pragma unroll
    for (int j = 0; j < 8; j++) bias[j] = __ldg(&bsum[n0 + tx * 8 + j]);
    #pragma unroll
    for (int i = 0; i < 8; i++) {
        size_t m = (size_t)(m0 + ty * 8 + i);
        float o[8];
        #pragma unroll
        for (int jp = 0; jp < 4; jp++) {
            float2 v = unpk(acc[i][jp]);
            o[2 * jp] = v.x + bias[2 * jp];
            o[2 * jp + 1] = v.y + bias[2 * jp + 1];
        }
        float4* dst = reinterpret_cast<float4*>(&GXo[m * 1024 + n0 + tx * 8]);
        dst[0] = make_float4(o[0], o[1], o[2], o[3]);
        dst[1] = make_float4(o[4], o[5], o[6], o[7]);
    }
}

// ---------------- persistent LSTM scan (DSMEM flag pipeline) ----------------
// 16 clusters of 8 CTAs (cluster = one batch element). CTA rank owns hidden
// units [rank*32, rank*32+32) for all 4 gates = 128 W_hh rows in registers.
// Sync per step: monotonic flags[8] (one per producer CTA) written with
// st.release.cluster, consumed with ld.acquire.cluster spin. No cluster
// barrier, no mbarrier -> no serialized arrivals, no store-drain at a barrier.
__global__ void __cluster_dims__(8, 1, 1) __launch_bounds__(256, 1)
scan_kernel(const float* __restrict__ Xin, const float* __restrict__ GX,
            const float* __restrict__ Whh, float* __restrict__ Xout, int is_even)
{
    unsigned rank;
    asm("mov.u32 %0, %%cluster_ctarank;" : "=r"(rank));
    const int b = blockIdx.x >> 3;
    const int tid = threadIdx.x;
    const int warp = tid >> 5, lane = tid & 31;
    const int lo = lane & 15, kh = lane >> 4;
    const int r = warp * 16 + lo;           // 0..127
    const int gidx = r >> 5, u = r & 31;
    const int grow = gidx * 256 + (int)rank * 32 + u;

    __shared__ __align__(16) float h_s[2][256];
    __shared__ float act_s[128];
    __shared__ __align__(16) unsigned flags[8];   // steps completed by CTA p

    const unsigned sb      = (unsigned)__cvta_generic_to_shared(&h_s[0][0]);
    const unsigned flags_a = (unsigned)__cvta_generic_to_shared(&flags[0]);

    // 128 fp32 weights per thread, register-resident
    ulonglong2 w[32];
    const ulonglong2* wp = reinterpret_cast<const ulonglong2*>(Whh + (size_t)grow * 256 + kh * 128);
    #pragma unroll
    for (int i = 0; i < 32; i++) w[i] = wp[i];

    h_s[0][tid] = 0.f;
    if (tid < 8) flags[tid] = 0u;
    float c_state = 0.f;
    __syncthreads();
    CLUSTER_SYNC();   // peers' flag init must precede any incoming flag store

    const float* gxp = GX + (size_t)b * 1024 + grow;
    float gxv = (kh == 0) ? __ldg(gxp) : 0.f;

    const unsigned my_flag_a = flags_a + 4u * rank;
    const unsigned poll_a    = flags_a + 4u * (unsigned)(lane & 7);

    for (int t = 0; t < Tn; ++t) {
        // wait until every CTA (incl. self) has published step t
        if (t) {
            const unsigned tgt = (unsigned)t;
            while (!__all_sync(0xffffffffu, ld_flag_acq(poll_a) >= tgt)) {}
        }

        // prefetch next step's gx (consumed one step later -> DRAM hidden)
        float gx_n = 0.f;
        if (kh == 0 && t + 1 < Tn) gx_n = __ldg(gxp + (size_t)(t + 1) * (Bn * G4));
        int src, dst;
        if (is_even) { dst = (t % 400) * 10 + (t / 400); src = dst; }
        else         { src = t; dst = Tn - 1 - t; }
        float xres = 0.f;
        if (tid < 32)
            xres = __ldg(Xin + ((size_t)src * Bn + b) * Cn + (int)rank * 32 + tid);

        // split-K dot (128 MACs/thread via FFMA2), halves reduced by shfl
        const int par = t & 1;
        const ulonglong2* h2 = reinterpret_cast<const ulonglong2*>(&h_s[par][kh << 7]);
        unsigned long long a0 = 0ull, a1 = 0ull, a2 = 0ull, a3 = 0ull;
        #pragma unroll
        for (int i = 0; i < 32; i += 4) {
            ulonglong2 x0 = h2[i], x1 = h2[i + 1], x2 = h2[i + 2], x3 = h2[i + 3];
            ffma2(a0, w[i].x,     x0.x); ffma2(a1, w[i].y,     x0.y);
            ffma2(a2, w[i + 1].x, x1.x); ffma2(a3, w[i + 1].y, x1.y);
            ffma2(a0, w[i + 2].x, x2.x); ffma2(a1, w[i + 2].y, x2.y);
            ffma2(a2, w[i + 3].x, x3.x); ffma2(a3, w[i + 3].y, x3.y);
        }
        float2 f0 = unpk(a0), f1 = unpk(a1), f2 = unpk(a2), f3 = unpk(a3);
        float partial = ((f0.x + f0.y) + (f1.x + f1.y)) + ((f2.x + f2.y) + (f3.x + f3.y));
        partial += __shfl_xor_sync(0xffffffffu, partial, 16);

        if (kh == 0) {
            float tot = partial + gxv;
            act_s[r] = (gidx == 2) ? tanh_f(tot) : sig_f(tot);
        }
        gxv = gx_n;
        __syncthreads();   // publish act_s to warp 0

        if (warp == 0) {
            float iv = act_s[lane], fv = act_s[32 + lane],
                  gv = act_s[64 + lane], ov = act_s[96 + lane];
            c_state = fv * c_state + iv * gv;
            float hv = ov * tanh_f(c_state);
            const int nb = par ^ 1;
            const int col = (int)rank * 32 + lane;
            h_s[nb][col] = hv;
            __syncwarp();
            if (t + 1 < Tn) {
                const unsigned stepv = (unsigned)(t + 1);
                if (lane < 7) {
                    // each of 7 lanes owns one peer: 8x 16B vector pushes + release flag
                    const unsigned p = (rank + 1u + (unsigned)lane) & 7u;
                    const float4* srcv = reinterpret_cast<const float4*>(&h_s[nb][(int)rank * 32]);
                    const unsigned dsta = sb + (unsigned)((nb * 256 + (int)rank * 32) * 4);
                    #pragma unroll
                    for (int k = 0; k < 8; k++)
                        st_peer_v4(dsta + 16u * k, p, srcv[k]);
                    st_flag_peer_rel(my_flag_a, p, stepv);
                } else if (lane == 7) {
                    st_flag_local_rel(my_flag_a, stepv);   // publish to own warps
                }
            }
            Xout[((size_t)dst * Bn + b) * Cn + col] = xres + hv;
        }
    }
}

// ---------------- launch ----------------
extern "C" void kernel_launch(void* const* d_in, const int* in_sizes, int n_in,
                              void* d_out, int out_size) {
    const float* x    = (const float*)d_in[0];
    const float* w_ih = (const float*)d_in[1];
    const float* w_hh = (const float*)d_in[2];
    const float* b_ih = (const float*)d_in[3];
    const float* b_hh = (const float*)d_in[4];

    float *Xa, *Xb, *GXp, *Bp;
    cudaGetSymbolAddress((void**)&Xa, g_Xa);
    cudaGetSymbolAddress((void**)&Xb, g_Xb);
    cudaGetSymbolAddress((void**)&GXp, g_GX);
    cudaGetSymbolAddress((void**)&Bp, g_bias);
    float* Xbuf[2] = {Xa, Xb};

    bias_kernel<<<NLAYER * G4 / 256, 256>>>(b_ih, b_hh, Bp);

    dim3 tgrid(Tn / 32, Cn / 32, Bn), tblk(32, 8);
    tin_kernel<<<tgrid, tblk>>>(x, Xbuf[0]);

    int cur = 0;
    for (int l = 0; l < NLAYER; ++l) {
        gemm_gx<<<dim3(G4 / 128, Mn / 128), 256>>>(
            Xbuf[cur], w_ih + (size_t)l * G4 * Cn, Bp + (size_t)l * G4, GXp);
        scan_kernel<<<128, 256>>>(
            Xbuf[cur], GXp, w_hh + (size_t)l * G4 * Cn,
            Xbuf[cur ^ 1], (l & 1) == 0 ? 1 : 0);
        cur ^= 1;
    }

    tout_kernel<<<tgrid, tblk>>>(Xbuf[cur], (float*)d_out);
}

// round 6
// speedup vs baseline: 1.7502x; 1.6425x over previous
#include <cuda_runtime.h>
#include <cstdint>

#define Tn 4000
#define Bn 16
#define Cn 256
#define G4 1024        // 4*C
#define Mn (Tn*Bn)     // 64000
#define NLAYER 12
#define NBPC 4         // batches per cluster
#define NCLUSTER (Bn / NBPC)   // 4 clusters of 8 CTAs

// ---------------- scratch (device globals: allocation-free) ----------------
__device__ float g_Xa[(size_t)Mn * Cn];
__device__ float g_Xb[(size_t)Mn * Cn];
__device__ float g_GX[(size_t)Mn * G4];
__device__ float g_bias[NLAYER * G4];

// ---------------- packed f32x2 helpers ----------------
__device__ __forceinline__ void ffma2(unsigned long long& d, unsigned long long a, unsigned long long b) {
    asm("fma.rn.f32x2 %0, %1, %2, %0;" : "+l"(d) : "l"(a), "l"(b));
}
__device__ __forceinline__ unsigned long long pk(float a, float b) {
    unsigned long long r; asm("mov.b64 %0, {%1,%2};" : "=l"(r) : "f"(a), "f"(b)); return r;
}
__device__ __forceinline__ float2 unpk(unsigned long long v) {
    float2 r; asm("mov.b64 {%0,%1}, %2;" : "=f"(r.x), "=f"(r.y) : "l"(v)); return r;
}

__device__ __forceinline__ float sig_f(float x) {
    return __fdividef(1.f, 1.f + __expf(-x));
}
__device__ __forceinline__ float tanh_f(float x) {
    float z = __expf(-2.f * fabsf(x));
    float t = __fdividef(1.f - z, 1.f + z);
    return (x < 0.f) ? -t : t;
}

// ---------------- cluster primitives ----------------
__device__ __forceinline__ void st_peer(unsigned laddr, unsigned peer, float v) {
    asm volatile(
        "{\n\t.reg .u32 ra;\n\t"
        "mapa.shared::cluster.u32 ra, %0, %1;\n\t"
        "st.shared::cluster.f32 [ra], %2;\n\t}"
        :: "r"(laddr), "r"(peer), "f"(v) : "memory");
}
#define CLUSTER_SYNC() do { \
    asm volatile("barrier.cluster.arrive.aligned;" ::: "memory"); \
    asm volatile("barrier.cluster.wait.aligned;" ::: "memory"); } while (0)

// ---------------- tiny bias precompute ----------------
__global__ void bias_kernel(const float* __restrict__ bih, const float* __restrict__ bhh,
                            float* __restrict__ out) {
    int i = blockIdx.x * 256 + threadIdx.x;
    out[i] = bih[i] + bhh[i];
}

// ---------------- transpose in: x(B,C,L) -> X[t][b][c] ----------------
__global__ void tin_kernel(const float* __restrict__ x, float* __restrict__ X) {
    __shared__ float tile[32][33];
    int t0 = blockIdx.x * 32, c0 = blockIdx.y * 32, b = blockIdx.z;
    int tx = threadIdx.x, ty = threadIdx.y;
    #pragma unroll
    for (int i = 0; i < 32; i += 8)
        tile[ty + i][tx] = x[(size_t)b * Cn * Tn + (size_t)(c0 + ty + i) * Tn + t0 + tx];
    __syncthreads();
    #pragma unroll
    for (int i = 0; i < 32; i += 8)
        X[(size_t)(t0 + ty + i) * Bn * Cn + b * Cn + c0 + tx] = tile[tx][ty + i];
}

// ---------------- transpose out: X[t][b][c] -> out(B,C,L) ----------------
__global__ void tout_kernel(const float* __restrict__ X, float* __restrict__ out) {
    __shared__ float tile[32][33];
    int t0 = blockIdx.x * 32, c0 = blockIdx.y * 32, b = blockIdx.z;
    int tx = threadIdx.x, ty = threadIdx.y;
    #pragma unroll
    for (int i = 0; i < 32; i += 8)
        tile[ty + i][tx] = X[(size_t)(t0 + ty + i) * Bn * Cn + b * Cn + c0 + tx];
    __syncthreads();
    #pragma unroll
    for (int i = 0; i < 32; i += 8)
        out[(size_t)b * Cn * Tn + (size_t)(c0 + ty + i) * Tn + t0 + tx] = tile[tx][ty + i];
}

// ---------------- gx GEMM: GX[m][n] = X[m][k]*W[n][k] + bias[n] ----------------
__global__ __launch_bounds__(256, 2) void gemm_gx(
    const float* __restrict__ X, const float* __restrict__ W,
    const float* __restrict__ bsum, float* __restrict__ GXo)
{
    __shared__ __align__(16) float As[2][8][128];
    __shared__ __align__(16) float Bs[2][8][128];
    const int m0 = blockIdx.y * 128;
    const int n0 = blockIdx.x * 128;
    const int tid = threadIdx.x;
    const int tx = tid & 15, ty = tid >> 4;
    const int lr = tid >> 1;           // 0..127
    const int lk = (tid & 1) * 4;      // 0 or 4

    const float* Ag = X + (size_t)(m0 + lr) * 256 + lk;
    const float* Bg = W + (size_t)(n0 + lr) * 256 + lk;

    auto load_stage = [&](int s, int kc) {
        float4 av = *reinterpret_cast<const float4*>(Ag + kc * 8);
        float4 bv = *reinterpret_cast<const float4*>(Bg + kc * 8);
        As[s][lk + 0][lr] = av.x; As[s][lk + 1][lr] = av.y;
        As[s][lk + 2][lr] = av.z; As[s][lk + 3][lr] = av.w;
        Bs[s][lk + 0][lr] = bv.x; Bs[s][lk + 1][lr] = bv.y;
        Bs[s][lk + 2][lr] = bv.z; Bs[s][lk + 3][lr] = bv.w;
    };

    unsigned long long acc[8][4];
    #pragma unroll
    for (int i = 0; i < 8; i++)
        #pragma unroll
        for (int j = 0; j < 4; j++) acc[i][j] = 0ull;

    load_stage(0, 0);
    __syncthreads();

    for (int kc = 0; kc < 32; ++kc) {
        int s = kc & 1;
        if (kc < 31) load_stage(s ^ 1, kc + 1);
        #pragma unroll
        for (int k = 0; k < 8; k++) {
            float4 a0 = *reinterpret_cast<const float4*>(&As[s][k][ty * 8]);
            float4 a1 = *reinterpret_cast<const float4*>(&As[s][k][ty * 8 + 4]);
            float4 b0 = *reinterpret_cast<const float4*>(&Bs[s][k][tx * 8]);
            float4 b1 = *reinterpret_cast<const float4*>(&Bs[s][k][tx * 8 + 4]);
            unsigned long long bb0 = pk(b0.x, b0.y), bb1 = pk(b0.z, b0.w);
            unsigned long long bb2 = pk(b1.x, b1.y), bb3 = pk(b1.z, b1.w);
            float av[8] = {a0.x, a0.y, a0.z, a0.w, a1.x, a1.y, a1.z, a1.w};
            #pragma unroll
            for (int i = 0; i < 8; i++) {
                unsigned long long aa = pk(av[i], av[i]);
                ffma2(acc[i][0], aa, bb0);
                ffma2(acc[i][1], aa, bb1);
                ffma2(acc[i][2], aa, bb2);
                ffma2(acc[i][3], aa, bb3);
            }
        }
        __syncthreads();
    }

    float bias[8];
    #pragma unroll
    for (int j = 0; j < 8; j++) bias[j] = __ldg(&bsum[n0 + tx * 8 + j]);
    #pragma unroll
    for (int i = 0; i < 8; i++) {
        size_t m = (size_t)(m0 + ty * 8 + i);
        float o[8];
        #pragma unroll
        for (int jp = 0; jp < 4; jp++) {
            float2 v = unpk(acc[i][jp]);
            o[2 * jp] = v.x + bias[2 * jp];
            o[2 * jp + 1] = v.y + bias[2 * jp + 1];
        }
        float4* dst = reinterpret_cast<float4*>(&GXo[m * 1024 + n0 + tx * 8]);
        dst[0] = make_float4(o[0], o[1], o[2], o[3]);
        dst[1] = make_float4(o[4], o[5], o[6], o[7]);
    }
}

// ---------------- persistent LSTM scan: 4 batches per cluster ----------------
// 4 clusters of 8 CTAs; cluster cl advances batches {cl*4 .. cl*4+3} together.
// CTA rank owns hidden units [rank*32, rank*32+32) for all 4 gates: 128 W_hh
// rows register-resident (shared across the 4 batches). Per step-group:
// fused 4-batch dot -> one __syncthreads -> warps 0..3 each update one batch's
// (h,c) and push its 32 h values to 7 peers -> ONE barrier.cluster for all 4.
__global__ void __cluster_dims__(8, 1, 1) __launch_bounds__(256, 1)
scan_kernel(const float* __restrict__ Xin, const float* __restrict__ GX,
            const float* __restrict__ Whh, float* __restrict__ Xout, int is_even)
{
    unsigned rank;
    asm("mov.u32 %0, %%cluster_ctarank;" : "=r"(rank));
    const int cl = blockIdx.x >> 3;           // cluster id 0..3
    const int b0 = cl * NBPC;                 // first batch of this cluster
    const int tid = threadIdx.x;
    const int warp = tid >> 5, lane = tid & 31;
    const int lo = lane & 15, kh = lane >> 4;
    const int r = warp * 16 + lo;             // 0..127 (gate*32 + unit)
    const int gidx = r >> 5, u = r & 31;
    const int grow = gidx * 256 + (int)rank * 32 + u;

    __shared__ __align__(16) float h_s[2][NBPC][256];
    __shared__ float act_s[NBPC][128];

    // 128 fp32 weights per thread, register-resident (shared by all batches)
    ulonglong2 w[32];
    const ulonglong2* wp = reinterpret_cast<const ulonglong2*>(Whh + (size_t)grow * 256 + kh * 128);
    #pragma unroll
    for (int i = 0; i < 32; i++) w[i] = wp[i];

    #pragma unroll
    for (int j = 0; j < NBPC; j++) h_s[0][j][tid] = 0.f;
    float c_state = 0.f;
    __syncthreads();
    CLUSTER_SYNC();

    // gx pointers: GX[(t*Bn + b0+j)*1024 + grow]
    const float* gxp = GX + (size_t)b0 * G4 + grow;
    float gxv[NBPC];
    if (kh == 0) {
        #pragma unroll
        for (int j = 0; j < NBPC; j++) gxv[j] = __ldg(gxp + j * G4);
    }

    for (int t = 0; t < Tn; ++t) {
        // prefetch next step's gx (consumed one full group later)
        float gxn[NBPC];
        if (kh == 0 && t + 1 < Tn) {
            const float* p = gxp + (size_t)(t + 1) * (Bn * G4);
            #pragma unroll
            for (int j = 0; j < NBPC; j++) gxn[j] = __ldg(p + j * G4);
        }
        int src, dst;
        if (is_even) { dst = (t % 400) * 10 + (t / 400); src = dst; }
        else         { src = t; dst = Tn - 1 - t; }
        float xres = 0.f;
        if (warp < NBPC)   // warp j prefetches residual for batch j
            xres = __ldg(Xin + ((size_t)src * Bn + b0 + warp) * Cn + (int)rank * 32 + lane);

        // fused 4-batch split-K dot: 512 MACs/thread via FFMA2
        const int par = t & 1;
        const float* hbase = &h_s[par][0][kh << 7];
        const ulonglong2* hA = reinterpret_cast<const ulonglong2*>(hbase);
        const ulonglong2* hB = reinterpret_cast<const ulonglong2*>(hbase + 256);
        const ulonglong2* hC = reinterpret_cast<const ulonglong2*>(hbase + 512);
        const ulonglong2* hD = reinterpret_cast<const ulonglong2*>(hbase + 768);
        unsigned long long aA0 = 0, aA1 = 0, aB0 = 0, aB1 = 0;
        unsigned long long aC0 = 0, aC1 = 0, aD0 = 0, aD1 = 0;
        #pragma unroll
        for (int i = 0; i < 32; i++) {
            ulonglong2 xA = hA[i], xB = hB[i], xC = hC[i], xD = hD[i];
            ffma2(aA0, w[i].x, xA.x); ffma2(aA1, w[i].y, xA.y);
            ffma2(aB0, w[i].x, xB.x); ffma2(aB1, w[i].y, xB.y);
            ffma2(aC0, w[i].x, xC.x); ffma2(aC1, w[i].y, xC.y);
            ffma2(aD0, w[i].x, xD.x); ffma2(aD1, w[i].y, xD.y);
        }
        float p[NBPC];
        { float2 f = unpk(aA0), g = unpk(aA1); p[0] = (f.x + f.y) + (g.x + g.y); }
        { float2 f = unpk(aB0), g = unpk(aB1); p[1] = (f.x + f.y) + (g.x + g.y); }
        { float2 f = unpk(aC0), g = unpk(aC1); p[2] = (f.x + f.y) + (g.x + g.y); }
        { float2 f = unpk(aD0), g = unpk(aD1); p[3] = (f.x + f.y) + (g.x + g.y); }
        #pragma unroll
        for (int j = 0; j < NBPC; j++)
            p[j] += __shfl_xor_sync(0xffffffffu, p[j], 16);

        if (kh == 0) {
            #pragma unroll
            for (int j = 0; j < NBPC; j++) {
                float tot = p[j] + gxv[j];
                act_s[j][r] = (gidx == 2) ? tanh_f(tot) : sig_f(tot);
            }
        }
        if (kh == 0) {
            #pragma unroll
            for (int j = 0; j < NBPC; j++) gxv[j] = gxn[j];
        }
        __syncthreads();   // publish act_s to warps 0..3

        if (warp < NBPC) { // warp j owns batch j (c_state lives in its lanes)
            const int j = warp;
            float iv = act_s[j][lane], fv = act_s[j][32 + lane],
                  gv = act_s[j][64 + lane], ov = act_s[j][96 + lane];
            c_state = fv * c_state + iv * gv;
            float hv = ov * tanh_f(c_state);
            const int nb = par ^ 1;
            const int col = (int)rank * 32 + lane;
            h_s[nb][j][col] = hv;
            if (t + 1 < Tn) {
                unsigned laddr = (unsigned)__cvta_generic_to_shared(&h_s[nb][j][col]);
                #pragma unroll
                for (unsigned q = 1; q < 8; q++)
                    st_peer(laddr, (rank + q) & 7u, hv);
            }
            Xout[((size_t)dst * Bn + b0 + j) * Cn + col] = xres + hv;
        }

        // one cluster barrier covers all 4 batches' exchanges
        CLUSTER_SYNC();
    }
}

// ---------------- launch ----------------
extern "C" void kernel_launch(void* const* d_in, const int* in_sizes, int n_in,
                              void* d_out, int out_size) {
    const float* x    = (const float*)d_in[0];
    const float* w_ih = (const float*)d_in[1];
    const float* w_hh = (const float*)d_in[2];
    const float* b_ih = (const float*)d_in[3];
    const float* b_hh = (const float*)d_in[4];

    float *Xa, *Xb, *GXp, *Bp;
    cudaGetSymbolAddress((void**)&Xa, g_Xa);
    cudaGetSymbolAddress((void**)&Xb, g_Xb);
    cudaGetSymbolAddress((void**)&GXp, g_GX);
    cudaGetSymbolAddress((void**)&Bp, g_bias);
    float* Xbuf[2] = {Xa, Xb};

    bias_kernel<<<NLAYER * G4 / 256, 256>>>(b_ih, b_hh, Bp);

    dim3 tgrid(Tn / 32, Cn / 32, Bn), tblk(32, 8);
    tin_kernel<<<tgrid, tblk>>>(x, Xbuf[0]);

    int cur = 0;
    for (int l = 0; l < NLAYER; ++l) {
        gemm_gx<<<dim3(G4 / 128, Mn / 128), 256>>>(
            Xbuf[cur], w_ih + (size_t)l * G4 * Cn, Bp + (size_t)l * G4, GXp);
        scan_kernel<<<NCLUSTER * 8, 256>>>(
            Xbuf[cur], GXp, w_hh + (size_t)l * G4 * Cn,
            Xbuf[cur ^ 1], (l & 1) == 0 ? 1 : 0);
        cur ^= 1;
    }

    tout_kernel<<<tgrid, tblk>>>(Xbuf[cur], (float*)d_out);
}

// round 7
// speedup vs baseline: 2.4645x; 1.4081x over previous
#include <cuda_runtime.h>
#include <cstdint>

#define Tn 4000
#define Bn 16
#define Cn 256
#define G4 1024        // 4*C
#define Mn (Tn*Bn)     // 64000
#define NLAYER 12
#define NBPC 2         // batches per cluster
#define NCLUSTER (Bn / NBPC)   // 8 clusters of 8 CTAs = 64 CTAs

// ---------------- scratch (device globals: allocation-free) ----------------
__device__ float g_Xa[(size_t)Mn * Cn];
__device__ float g_Xb[(size_t)Mn * Cn];
__device__ float g_GX[(size_t)Mn * G4];
__device__ float g_bias[NLAYER * G4];

// ---------------- packed f32x2 helpers ----------------
__device__ __forceinline__ void ffma2(unsigned long long& d, unsigned long long a, unsigned long long b) {
    asm("fma.rn.f32x2 %0, %1, %2, %0;" : "+l"(d) : "l"(a), "l"(b));
}
__device__ __forceinline__ unsigned long long pk(float a, float b) {
    unsigned long long r; asm("mov.b64 %0, {%1,%2};" : "=l"(r) : "f"(a), "f"(b)); return r;
}
__device__ __forceinline__ float2 unpk(unsigned long long v) {
    float2 r; asm("mov.b64 {%0,%1}, %2;" : "=f"(r.x), "=f"(r.y) : "l"(v)); return r;
}

__device__ __forceinline__ float sig_f(float x) {
    return __fdividef(1.f, 1.f + __expf(-x));
}
__device__ __forceinline__ float tanh_f(float x) {
    float z = __expf(-2.f * fabsf(x));
    float t = __fdividef(1.f - z, 1.f + z);
    return (x < 0.f) ? -t : t;
}

// ---------------- cluster primitives ----------------
__device__ __forceinline__ void st_peer(unsigned laddr, unsigned peer, float v) {
    asm volatile(
        "{\n\t.reg .u32 ra;\n\t"
        "mapa.shared::cluster.u32 ra, %0, %1;\n\t"
        "st.shared::cluster.f32 [ra], %2;\n\t}"
        :: "r"(laddr), "r"(peer), "f"(v) : "memory");
}
#define CLUSTER_SYNC() do { \
    asm volatile("barrier.cluster.arrive.aligned;" ::: "memory"); \
    asm volatile("barrier.cluster.wait.aligned;" ::: "memory"); } while (0)

// ---------------- tiny bias precompute ----------------
__global__ void bias_kernel(const float* __restrict__ bih, const float* __restrict__ bhh,
                            float* __restrict__ out) {
    int i = blockIdx.x * 256 + threadIdx.x;
    out[i] = bih[i] + bhh[i];
}

// ---------------- transpose in: x(B,C,L) -> X[t][b][c] ----------------
__global__ void tin_kernel(const float* __restrict__ x, float* __restrict__ X) {
    __shared__ float tile[32][33];
    int t0 = blockIdx.x * 32, c0 = blockIdx.y * 32, b = blockIdx.z;
    int tx = threadIdx.x, ty = threadIdx.y;
    #pragma unroll
    for (int i = 0; i < 32; i += 8)
        tile[ty + i][tx] = x[(size_t)b * Cn * Tn + (size_t)(c0 + ty + i) * Tn + t0 + tx];
    __syncthreads();
    #pragma unroll
    for (int i = 0; i < 32; i += 8)
        X[(size_t)(t0 + ty + i) * Bn * Cn + b * Cn + c0 + tx] = tile[tx][ty + i];
}

// ---------------- transpose out: X[t][b][c] -> out(B,C,L) ----------------
__global__ void tout_kernel(const float* __restrict__ X, float* __restrict__ out) {
    __shared__ float tile[32][33];
    int t0 = blockIdx.x * 32, c0 = blockIdx.y * 32, b = blockIdx.z;
    int tx = threadIdx.x, ty = threadIdx.y;
    #pragma unroll
    for (int i = 0; i < 32; i += 8)
        tile[ty + i][tx] = X[(size_t)(t0 + ty + i) * Bn * Cn + b * Cn + c0 + tx];
    __syncthreads();
    #pragma unroll
    for (int i = 0; i < 32; i += 8)
        out[(size_t)b * Cn * Tn + (size_t)(c0 + ty + i) * Tn + t0 + tx] = tile[tx][ty + i];
}

// ---------------- gx GEMM: GX[m][n] = X[m][k]*W[n][k] + bias[n] ----------------
__global__ __launch_bounds__(256, 2) void gemm_gx(
    const float* __restrict__ X, const float* __restrict__ W,
    const float* __restrict__ bsum, float* __restrict__ GXo)
{
    __shared__ __align__(16) float As[2][8][128];
    __shared__ __align__(16) float Bs[2][8][128];
    const int m0 = blockIdx.y * 128;
    const int n0 = blockIdx.x * 128;
    const int tid = threadIdx.x;
    const int tx = tid & 15, ty = tid >> 4;
    const int lr = tid >> 1;           // 0..127
    const int lk = (tid & 1) * 4;      // 0 or 4

    const float* Ag = X + (size_t)(m0 + lr) * 256 + lk;
    const float* Bg = W + (size_t)(n0 + lr) * 256 + lk;

    auto load_stage = [&](int s, int kc) {
        float4 av = *reinterpret_cast<const float4*>(Ag + kc * 8);
        float4 bv = *reinterpret_cast<const float4*>(Bg + kc * 8);
        As[s][lk + 0][lr] = av.x; As[s][lk + 1][lr] = av.y;
        As[s][lk + 2][lr] = av.z; As[s][lk + 3][lr] = av.w;
        Bs[s][lk + 0][lr] = bv.x; Bs[s][lk + 1][lr] = bv.y;
        Bs[s][lk + 2][lr] = bv.z; Bs[s][lk + 3][lr] = bv.w;
    };

    unsigned long long acc[8][4];
    #pragma unroll
    for (int i = 0; i < 8; i++)
        #pragma unroll
        for (int j = 0; j < 4; j++) acc[i][j] = 0ull;

    load_stage(0, 0);
    __syncthreads();

    for (int kc = 0; kc < 32; ++kc) {
        int s = kc & 1;
        if (kc < 31) load_stage(s ^ 1, kc + 1);
        #pragma unroll
        for (int k = 0; k < 8; k++) {
            float4 a0 = *reinterpret_cast<const float4*>(&As[s][k][ty * 8]);
            float4 a1 = *reinterpret_cast<const float4*>(&As[s][k][ty * 8 + 4]);
            float4 b0 = *reinterpret_cast<const float4*>(&Bs[s][k][tx * 8]);
            float4 b1 = *reinterpret_cast<const float4*>(&Bs[s][k][tx * 8 + 4]);
            unsigned long long bb0 = pk(b0.x, b0.y), bb1 = pk(b0.z, b0.w);
            unsigned long long bb2 = pk(b1.x, b1.y), bb3 = pk(b1.z, b1.w);
            float av[8] = {a0.x, a0.y, a0.z, a0.w, a1.x, a1.y, a1.z, a1.w};
            #pragma unroll
            for (int i = 0; i < 8; i++) {
                unsigned long long aa = pk(av[i], av[i]);
                ffma2(acc[i][0], aa, bb0);
                ffma2(acc[i][1], aa, bb1);
                ffma2(acc[i][2], aa, bb2);
                ffma2(acc[i][3], aa, bb3);
            }
        }
        __syncthreads();
    }

    float bias[8];
    #pragma unroll
    for (int j = 0; j < 8; j++) bias[j] = __ldg(&bsum[n0 + tx * 8 + j]);
    #pragma unroll
    for (int i = 0; i < 8; i++) {
        size_t m = (size_t)(m0 + ty * 8 + i);
        float o[8];
        #pragma unroll
        for (int jp = 0; jp < 4; jp++) {
            float2 v = unpk(acc[i][jp]);
            o[2 * jp] = v.x + bias[2 * jp];
            o[2 * jp + 1] = v.y + bias[2 * jp + 1];
        }
        float4* dst = reinterpret_cast<float4*>(&GXo[m * 1024 + n0 + tx * 8]);
        dst[0] = make_float4(o[0], o[1], o[2], o[3]);
        dst[1] = make_float4(o[4], o[5], o[6], o[7]);
    }
}

// ---------------- persistent LSTM scan: gate-per-lane, no syncthreads ----------------
// 8 clusters of 8 CTAs; cluster cl advances batches {cl*2, cl*2+1}.
// CTA rank owns units [rank*32, rank*32+32). Warp w owns units w*4..w*4+3.
// Lane layout: lo = lane&15 -> unit (lo>>2) of warp, gate (lo&3); kh = lane>>4
// is BOTH the K-half for the dot and the batch this lane updates.
// Per step: both-batch dot over K-half -> shfl.xor(16) fold (both halves get
// full sums) -> activation (one gate per lane) -> 4 shfl gather -> c/h update
// replicated per unit's 4 lanes -> peer pushes spread over lanes -> ONE
// barrier.cluster. No __syncthreads, no act smem round-trip.
__global__ void __cluster_dims__(8, 1, 1) __launch_bounds__(256, 1)
scan_kernel(const float* __restrict__ Xin, const float* __restrict__ GX,
            const float* __restrict__ Whh, float* __restrict__ Xout, int is_even)
{
    unsigned rank;
    asm("mov.u32 %0, %%cluster_ctarank;" : "=r"(rank));
    const int cl = blockIdx.x >> 3;
    const int b0 = cl * NBPC;
    const int tid = threadIdx.x;
    const int warp = tid >> 5, lane = tid & 31;
    const int lo = lane & 15, kh = lane >> 4;       // kh = K-half = batch index
    const int s = lo & 3;                            // gate index (i,f,g,o)
    const int unit = warp * 4 + (lo >> 2);           // 0..31 (unit within CTA)
    const int grow = s * 256 + (int)rank * 32 + unit;
    const int col = (int)rank * 32 + unit;
    const int bsel = b0 + kh;

    __shared__ __align__(16) float h_s[2][NBPC][256];

    // K-half weights for this lane's gate row: 128 fp32 register-resident
    ulonglong2 w[32];
    const ulonglong2* wp = reinterpret_cast<const ulonglong2*>(Whh + (size_t)grow * 256 + kh * 128);
    #pragma unroll
    for (int i = 0; i < 32; i++) w[i] = wp[i];

    h_s[0][0][tid] = 0.f;
    h_s[0][1][tid] = 0.f;
    float c_state = 0.f;
    __syncthreads();
    CLUSTER_SYNC();

    // gx for this lane's (row, batch)
    const float* gxp = GX + (size_t)bsel * G4 + grow;
    float gxv = __ldg(gxp);
    // residual prefetch (s==1 lanes store Xout)
    auto src_of = [&](int t) {
        return is_even ? (t % 400) * 10 + (t / 400) : t;
    };
    float xres = (s == 1) ? __ldg(Xin + ((size_t)src_of(0) * Bn + bsel) * Cn + col) : 0.f;

    for (int t = 0; t < Tn; ++t) {
        // prefetch next step's gx/xres (consumed next iteration)
        float gxn = 0.f, xresn = 0.f;
        if (t + 1 < Tn) {
            gxn = __ldg(gxp + (size_t)(t + 1) * (Bn * G4));
            if (s == 1)
                xresn = __ldg(Xin + ((size_t)src_of(t + 1) * Bn + bsel) * Cn + col);
        }
        const int dst = is_even ? (t % 400) * 10 + (t / 400) : (Tn - 1 - t);

        // both-batch dot over this lane's K-half (256 MACs via FFMA2)
        const int par = t & 1;
        const ulonglong2* hA = reinterpret_cast<const ulonglong2*>(&h_s[par][0][kh << 7]);
        const ulonglong2* hB = reinterpret_cast<const ulonglong2*>(&h_s[par][1][kh << 7]);
        unsigned long long a00 = 0, a01 = 0, a10 = 0, a11 = 0;
        #pragma unroll
        for (int i = 0; i < 32; i++) {
            ulonglong2 xA = hA[i], xB = hB[i];
            ffma2(a00, w[i].x, xA.x); ffma2(a01, w[i].y, xA.y);
            ffma2(a10, w[i].x, xB.x); ffma2(a11, w[i].y, xB.y);
        }
        float2 f0 = unpk(a00), f1 = unpk(a01);
        float p0 = (f0.x + f0.y) + (f1.x + f1.y);
        float2 f2 = unpk(a10), f3 = unpk(a11);
        float p1 = (f2.x + f2.y) + (f3.x + f3.y);
        // fold K-halves: afterwards BOTH halves hold full sums for both batches
        p0 += __shfl_xor_sync(0xffffffffu, p0, 16);
        p1 += __shfl_xor_sync(0xffffffffu, p1, 16);

        // this lane's batch = kh; activation of its gate
        float tot = (kh ? p1 : p0) + gxv;
        float act = (s == 2) ? tanh_f(tot) : sig_f(tot);
        gxv = gxn;

        // gather the 4 gates of this unit (within same half)
        const int base = lane & ~3;
        float iv = __shfl_sync(0xffffffffu, act, base);
        float fv = __shfl_sync(0xffffffffu, act, base | 1);
        float gv = __shfl_sync(0xffffffffu, act, base | 2);
        float ov = __shfl_sync(0xffffffffu, act, base | 3);

        c_state = fv * c_state + iv * gv;           // replicated across 4 lanes
        float hv = ov * tanh_f(c_state);

        const int nb = par ^ 1;
        if (s == 0) h_s[nb][kh][col] = hv;
        if (t + 1 < Tn) {
            unsigned laddr = (unsigned)__cvta_generic_to_shared(&h_s[nb][kh][col]);
            // peers {1..7} covered by lane's gate slot: s -> {s+1, s+5(if<8)}
            st_peer(laddr, (rank + (unsigned)s + 1u) & 7u, hv);
            if (s < 3)
                st_peer(laddr, (rank + (unsigned)s + 5u) & 7u, hv);
        }
        if (s == 1)
            Xout[((size_t)dst * Bn + bsel) * Cn + col] = xres + hv;
        xres = xresn;

        CLUSTER_SYNC();   // publishes DSMEM pushes + local h_s for next step
    }
}

// ---------------- launch ----------------
extern "C" void kernel_launch(void* const* d_in, const int* in_sizes, int n_in,
                              void* d_out, int out_size) {
    const float* x    = (const float*)d_in[0];
    const float* w_ih = (const float*)d_in[1];
    const float* w_hh = (const float*)d_in[2];
    const float* b_ih = (const float*)d_in[3];
    const float* b_hh = (const float*)d_in[4];

    float *Xa, *Xb, *GXp, *Bp;
    cudaGetSymbolAddress((void**)&Xa, g_Xa);
    cudaGetSymbolAddress((void**)&Xb, g_Xb);
    cudaGetSymbolAddress((void**)&GXp, g_GX);
    cudaGetSymbolAddress((void**)&Bp, g_bias);
    float* Xbuf[2] = {Xa, Xb};

    bias_kernel<<<NLAYER * G4 / 256, 256>>>(b_ih, b_hh, Bp);

    dim3 tgrid(Tn / 32, Cn / 32, Bn), tblk(32, 8);
    tin_kernel<<<tgrid, tblk>>>(x, Xbuf[0]);

    int cur = 0;
    for (int l = 0; l < NLAYER; ++l) {
        gemm_gx<<<dim3(G4 / 128, Mn / 128), 256>>>(
            Xbuf[cur], w_ih + (size_t)l * G4 * Cn, Bp + (size_t)l * G4, GXp);
        scan_kernel<<<NCLUSTER * 8, 256>>>(
            Xbuf[cur], GXp, w_hh + (size_t)l * G4 * Cn,
            Xbuf[cur ^ 1], (l & 1) == 0 ? 1 : 0);
        cur ^= 1;
    }

    tout_kernel<<<tgrid, tblk>>>(Xbuf[cur], (float*)d_out);
}